// round 9
// baseline (speedup 1.0000x reference)
#include <cuda_runtime.h>

#define NQ      14
#define DIM     16384      // 2^14
#define NPAIR   8192       // DIM/2
#define NLAYERS 2
#define NTHR    1024
#define NGATES  (NLAYERS * NQ)

struct cpx { float x, y; };

__device__ __forceinline__ cpx cmul(cpx a, cpx b) {
    return { a.x * b.x - a.y * b.y, a.x * b.y + a.y * b.x };
}
__device__ __forceinline__ cpx cadd(cpx a, cpx b) {
    return { a.x + b.x, a.y + b.y };
}
__device__ __forceinline__ void mmul2(const cpx* A, const cpx* B, cpx* C) {
    C[0] = cadd(cmul(A[0], B[0]), cmul(A[1], B[2]));
    C[1] = cadd(cmul(A[0], B[1]), cmul(A[1], B[3]));
    C[2] = cadd(cmul(A[2], B[0]), cmul(A[3], B[2]));
    C[3] = cadd(cmul(A[2], B[1]), cmul(A[3], B[3]));
}

__global__ __launch_bounds__(NTHR, 1)
void qsim_kernel(const float* __restrict__ x,
                 const float* __restrict__ thetas,
                 float* __restrict__ out) {
    extern __shared__ float smem[];
    float* re = smem;          // [DIM]
    float* im = smem + DIM;    // [DIM]
    __shared__ cpx  gates[NGATES][4];
    __shared__ float red[32];

    const int b   = blockIdx.x;
    const int tid = threadIdx.x;
    const float xb = x[b];

    // ---- init state |0...0> ----
    for (int k = tid; k < DIM; k += NTHR) { re[k] = 0.0f; im[k] = 0.0f; }
    if (tid == 0) re[0] = 1.0f;

    // ---- precompute fused single-qubit gates: one thread per (layer, q) ----
    // G = RX(t2) * RZ(t1) * RX(t0) * RZ(x2) * RY(x1)
    if (tid < NGATES) {
        const int layer = tid / NQ;
        const int q     = tid % NQ;

        const float x1 = asinf(xb);
        const float x2 = acosf(xb * xb);
        float s1, c1;  sincosf(0.5f * x1, &s1, &c1);
        float sz, cz;  sincosf(0.5f * x2, &sz, &cz);
        // M = RZ(x2) * RY(x1)
        cpx M[4] = { { cz * c1, -sz * c1 }, { -cz * s1,  sz * s1 },
                     { cz * s1,  sz * s1 }, {  cz * c1,  sz * c1 } };

        const float* th = thetas + (layer * NQ + q) * 3;
        float s0, c0;   sincosf(0.5f * th[0], &s0, &c0);
        float sr1, cr1; sincosf(0.5f * th[1], &sr1, &cr1);
        float s2, c2v;  sincosf(0.5f * th[2], &s2, &c2v);

        cpx RX0[4] = { { c0, 0.f }, { 0.f, -s0 }, { 0.f, -s0 }, { c0, 0.f } };
        cpx RZ1[4] = { { cr1, -sr1 }, { 0.f, 0.f }, { 0.f, 0.f }, { cr1, sr1 } };
        cpx RX2[4] = { { c2v, 0.f }, { 0.f, -s2 }, { 0.f, -s2 }, { c2v, 0.f } };

        cpx T1[4], T2[4], G[4];
        mmul2(RX0, M,  T1);
        mmul2(RZ1, T1, T2);
        mmul2(RX2, T2, G);
        gates[tid][0] = G[0]; gates[tid][1] = G[1];
        gates[tid][2] = G[2]; gates[tid][3] = G[3];
    }
    __syncthreads();

    // ---- circuit ----
    for (int layer = 0; layer < NLAYERS; layer++) {
        // 14 fused single-qubit gates
        for (int q = 0; q < NQ; q++) {
            const cpx g0 = gates[layer * NQ + q][0];
            const cpx g1 = gates[layer * NQ + q][1];
            const cpx g2 = gates[layer * NQ + q][2];
            const cpx g3 = gates[layer * NQ + q][3];
            const int s      = NQ - 1 - q;     // bit position of qubit q
            const int stride = 1 << s;

            #pragma unroll 4
            for (int p = tid; p < NPAIR; p += NTHR) {
                const int i0 = ((p >> s) << (s + 1)) | (p & (stride - 1));
                const int i1 = i0 + stride;
                const cpx a  = { re[i0], im[i0] };
                const cpx bb = { re[i1], im[i1] };
                const cpx na = cadd(cmul(g0, a), cmul(g1, bb));
                const cpx nb = cadd(cmul(g2, a), cmul(g3, bb));
                re[i0] = na.x; im[i0] = na.y;
                re[i1] = nb.x; im[i1] = nb.y;
            }
            __syncthreads();
        }

        // fused CNOT chain: out[i] = in[i ^ (i >> 1)]
        float tr[DIM / NTHR], ti[DIM / NTHR];
        #pragma unroll
        for (int k = 0; k < DIM / NTHR; k++) {
            const int i   = tid + k * NTHR;
            const int src = i ^ (i >> 1);
            tr[k] = re[src]; ti[k] = im[src];
        }
        __syncthreads();
        #pragma unroll
        for (int k = 0; k < DIM / NTHR; k++) {
            const int i = tid + k * NTHR;
            re[i] = tr[k]; im[i] = ti[k];
        }
        __syncthreads();
    }

    // ---- expectation <Z...Z> = sum_i parity(i) * |amp_i|^2 ----
    float acc = 0.0f;
    #pragma unroll
    for (int k = 0; k < DIM / NTHR; k++) {
        const int i = tid + k * NTHR;
        const float p2 = re[i] * re[i] + im[i] * im[i];
        acc += (__popc(i) & 1) ? -p2 : p2;
    }
    #pragma unroll
    for (int o = 16; o; o >>= 1) acc += __shfl_down_sync(0xffffffffu, acc, o);
    if ((tid & 31) == 0) red[tid >> 5] = acc;
    __syncthreads();
    if (tid < 32) {
        float v = red[tid];
        #pragma unroll
        for (int o = 16; o; o >>= 1) v += __shfl_down_sync(0xffffffffu, v, o);
        if (tid == 0) out[b] = v;
    }
}

extern "C" void kernel_launch(void* const* d_in, const int* in_sizes, int n_in,
                              void* d_out, int out_size) {
    const float* x      = (const float*)d_in[0];
    const float* thetas = (const float*)d_in[1];
    float* out          = (float*)d_out;

    const int smem_bytes = 2 * DIM * (int)sizeof(float);  // 131072
    cudaFuncSetAttribute(qsim_kernel,
                         cudaFuncAttributeMaxDynamicSharedMemorySize, smem_bytes);
    qsim_kernel<<<64, NTHR, smem_bytes>>>(x, thetas, out);
}

// round 10
// speedup vs baseline: 1.0052x; 1.0052x over previous
#include <cuda_runtime.h>

#define NQ      14
#define DIM     16384      // 2^14
#define NPAIR   8192       // DIM/2
#define NLAYERS 2
#define NTHR    1024
#define NGATES  (NLAYERS * NQ)

struct cpx { float x, y; };

__device__ __forceinline__ cpx cmul(cpx a, cpx b) {
    return { a.x * b.x - a.y * b.y, a.x * b.y + a.y * b.x };
}
__device__ __forceinline__ cpx cadd(cpx a, cpx b) {
    return { a.x + b.x, a.y + b.y };
}
__device__ __forceinline__ void mmul2(const cpx* A, const cpx* B, cpx* C) {
    C[0] = cadd(cmul(A[0], B[0]), cmul(A[1], B[2]));
    C[1] = cadd(cmul(A[0], B[1]), cmul(A[1], B[3]));
    C[2] = cadd(cmul(A[2], B[0]), cmul(A[3], B[2]));
    C[3] = cadd(cmul(A[2], B[1]), cmul(A[3], B[3]));
}

__global__ __launch_bounds__(NTHR, 1)
void qsim_kernel(const float* __restrict__ x,
                 const float* __restrict__ thetas,
                 float* __restrict__ out) {
    extern __shared__ float smem[];
    float* re = smem;          // [DIM]
    float* im = smem + DIM;    // [DIM]
    __shared__ cpx  gates[NGATES][4];
    __shared__ float red[32];

    const int b   = blockIdx.x;
    const int tid = threadIdx.x;
    const float xb = x[b];

    // ---- init state |0...0> ----
    for (int k = tid; k < DIM; k += NTHR) { re[k] = 0.0f; im[k] = 0.0f; }
    if (tid == 0) re[0] = 1.0f;

    // ---- precompute fused single-qubit gates: one thread per (layer, q) ----
    // G = RX(t2) * RZ(t1) * RX(t0) * RZ(x2) * RY(x1)
    if (tid < NGATES) {
        const int layer = tid / NQ;
        const int q     = tid % NQ;

        const float x1 = asinf(xb);
        const float x2 = acosf(xb * xb);
        float s1, c1;  sincosf(0.5f * x1, &s1, &c1);
        float sz, cz;  sincosf(0.5f * x2, &sz, &cz);
        // M = RZ(x2) * RY(x1)
        cpx M[4] = { { cz * c1, -sz * c1 }, { -cz * s1,  sz * s1 },
                     { cz * s1,  sz * s1 }, {  cz * c1,  sz * c1 } };

        const float* th = thetas + (layer * NQ + q) * 3;
        float s0, c0;   sincosf(0.5f * th[0], &s0, &c0);
        float sr1, cr1; sincosf(0.5f * th[1], &sr1, &cr1);
        float s2, c2v;  sincosf(0.5f * th[2], &s2, &c2v);

        cpx RX0[4] = { { c0, 0.f }, { 0.f, -s0 }, { 0.f, -s0 }, { c0, 0.f } };
        cpx RZ1[4] = { { cr1, -sr1 }, { 0.f, 0.f }, { 0.f, 0.f }, { cr1, sr1 } };
        cpx RX2[4] = { { c2v, 0.f }, { 0.f, -s2 }, { 0.f, -s2 }, { c2v, 0.f } };

        cpx T1[4], T2[4], G[4];
        mmul2(RX0, M,  T1);
        mmul2(RZ1, T1, T2);
        mmul2(RX2, T2, G);
        gates[tid][0] = G[0]; gates[tid][1] = G[1];
        gates[tid][2] = G[2]; gates[tid][3] = G[3];
    }
    __syncthreads();

    // ---- circuit ----
    for (int layer = 0; layer < NLAYERS; layer++) {
        // 14 fused single-qubit gates
        for (int q = 0; q < NQ; q++) {
            const cpx g0 = gates[layer * NQ + q][0];
            const cpx g1 = gates[layer * NQ + q][1];
            const cpx g2 = gates[layer * NQ + q][2];
            const cpx g3 = gates[layer * NQ + q][3];
            const int s      = NQ - 1 - q;     // bit position of qubit q
            const int stride = 1 << s;

            #pragma unroll 4
            for (int p = tid; p < NPAIR; p += NTHR) {
                const int i0 = ((p >> s) << (s + 1)) | (p & (stride - 1));
                const int i1 = i0 + stride;
                const cpx a  = { re[i0], im[i0] };
                const cpx bb = { re[i1], im[i1] };
                const cpx na = cadd(cmul(g0, a), cmul(g1, bb));
                const cpx nb = cadd(cmul(g2, a), cmul(g3, bb));
                re[i0] = na.x; im[i0] = na.y;
                re[i1] = nb.x; im[i1] = nb.y;
            }
            __syncthreads();
        }

        // fused CNOT chain: out[i] = in[i ^ (i >> 1)]
        float tr[DIM / NTHR], ti[DIM / NTHR];
        #pragma unroll
        for (int k = 0; k < DIM / NTHR; k++) {
            const int i   = tid + k * NTHR;
            const int src = i ^ (i >> 1);
            tr[k] = re[src]; ti[k] = im[src];
        }
        __syncthreads();
        #pragma unroll
        for (int k = 0; k < DIM / NTHR; k++) {
            const int i = tid + k * NTHR;
            re[i] = tr[k]; im[i] = ti[k];
        }
        __syncthreads();
    }

    // ---- expectation <Z...Z> = sum_i parity(i) * |amp_i|^2 ----
    float acc = 0.0f;
    #pragma unroll
    for (int k = 0; k < DIM / NTHR; k++) {
        const int i = tid + k * NTHR;
        const float p2 = re[i] * re[i] + im[i] * im[i];
        acc += (__popc(i) & 1) ? -p2 : p2;
    }
    #pragma unroll
    for (int o = 16; o; o >>= 1) acc += __shfl_down_sync(0xffffffffu, acc, o);
    if ((tid & 31) == 0) red[tid >> 5] = acc;
    __syncthreads();
    if (tid < 32) {
        float v = red[tid];
        #pragma unroll
        for (int o = 16; o; o >>= 1) v += __shfl_down_sync(0xffffffffu, v, o);
        if (tid == 0) out[b] = v;
    }
}

extern "C" void kernel_launch(void* const* d_in, const int* in_sizes, int n_in,
                              void* d_out, int out_size) {
    const float* x      = (const float*)d_in[0];
    const float* thetas = (const float*)d_in[1];
    float* out          = (float*)d_out;

    const int smem_bytes = 2 * DIM * (int)sizeof(float);  // 131072
    cudaFuncSetAttribute(qsim_kernel,
                         cudaFuncAttributeMaxDynamicSharedMemorySize, smem_bytes);
    qsim_kernel<<<64, NTHR, smem_bytes>>>(x, thetas, out);
}

// round 11
// speedup vs baseline: 1.4897x; 1.4820x over previous
#include <cuda_runtime.h>

#define NQ      14
#define DIM     16384      // 2^14
#define NLAYERS 2
#define NTHR    1024
#define NGATES  (NLAYERS * NQ)
#define SSZ     (DIM + DIM / 16)   // 17408 floats per array (pad-swizzle)

struct cpx { float x, y; };

__device__ __forceinline__ cpx cmul(cpx a, cpx b) {
    return { a.x * b.x - a.y * b.y, a.x * b.y + a.y * b.x };
}
__device__ __forceinline__ cpx cadd(cpx a, cpx b) {
    return { a.x + b.x, a.y + b.y };
}
__device__ __forceinline__ void mmul2(const cpx* A, const cpx* B, cpx* C) {
    C[0] = cadd(cmul(A[0], B[0]), cmul(A[1], B[2]));
    C[1] = cadd(cmul(A[0], B[1]), cmul(A[1], B[3]));
    C[2] = cadd(cmul(A[2], B[0]), cmul(A[3], B[2]));
    C[3] = cadd(cmul(A[2], B[1]), cmul(A[3], B[3]));
}

// pad-swizzle: one pad word per 16 -> stride-17 across thread dim kills the
// 16-way bank conflicts of the natural exchange patterns.
__device__ __forceinline__ int swz(int i) { return i + (i >> 4); }

// In-register butterfly on local v-bit K with gate G (4 complex coeffs).
template <int K>
__device__ __forceinline__ void apply_gate(float (&ar)[16], float (&ai)[16],
                                           const cpx* __restrict__ G) {
    const cpx g0 = G[0], g1 = G[1], g2 = G[2], g3 = G[3];
#pragma unroll
    for (int m = 0; m < 8; m++) {
        const int v0 = ((m >> K) << (K + 1)) | (m & ((1 << K) - 1));
        const int v1 = v0 | (1 << K);
        const float a_r = ar[v0], a_i = ai[v0];
        const float b_r = ar[v1], b_i = ai[v1];
        ar[v0] = g0.x * a_r - g0.y * a_i + g1.x * b_r - g1.y * b_i;
        ai[v0] = g0.x * a_i + g0.y * a_r + g1.x * b_i + g1.y * b_r;
        ar[v1] = g2.x * a_r - g2.y * a_i + g3.x * b_r - g3.y * b_i;
        ai[v1] = g2.x * a_i + g2.y * a_r + g3.x * b_i + g3.y * b_r;
    }
}

__global__ __launch_bounds__(NTHR, 1)
void qsim_kernel(const float* __restrict__ x,
                 const float* __restrict__ thetas,
                 float* __restrict__ out) {
    extern __shared__ float smem[];
    float* re = smem;          // [SSZ]
    float* im = smem + SSZ;    // [SSZ]
    __shared__ cpx  gates[NGATES][4];
    __shared__ float red[32];

    const int b = blockIdx.x;
    const int T = threadIdx.x;
    const float xb = x[b];

    // ---- fused single-qubit gates: G = RX(t2)*RZ(t1)*RX(t0)*RZ(x2)*RY(x1) ----
    if (T < NGATES) {
        const int layer = T / NQ;
        const int q     = T % NQ;

        const float x1 = asinf(xb);
        const float x2 = acosf(xb * xb);
        float s1, c1;  sincosf(0.5f * x1, &s1, &c1);
        float sz, cz;  sincosf(0.5f * x2, &sz, &cz);
        cpx M[4] = { { cz * c1, -sz * c1 }, { -cz * s1,  sz * s1 },
                     { cz * s1,  sz * s1 }, {  cz * c1,  sz * c1 } };

        const float* th = thetas + (layer * NQ + q) * 3;
        float s0, c0;   sincosf(0.5f * th[0], &s0, &c0);
        float sr1, cr1; sincosf(0.5f * th[1], &sr1, &cr1);
        float s2, c2v;  sincosf(0.5f * th[2], &s2, &c2v);

        cpx RX0[4] = { { c0, 0.f }, { 0.f, -s0 }, { 0.f, -s0 }, { c0, 0.f } };
        cpx RZ1[4] = { { cr1, -sr1 }, { 0.f, 0.f }, { 0.f, 0.f }, { cr1, sr1 } };
        cpx RX2[4] = { { c2v, 0.f }, { 0.f, -s2 }, { 0.f, -s2 }, { c2v, 0.f } };

        cpx T1[4], T2[4], G[4];
        mmul2(RX0, M,  T1);
        mmul2(RZ1, T1, T2);
        mmul2(RX2, T2, G);
        gates[T][0] = G[0]; gates[T][1] = G[1];
        gates[T][2] = G[2]; gates[T][3] = G[3];
    }
    __syncthreads();

    // ---- state lives in registers: 16 amplitudes per thread ----
    float ar[16], ai[16];
#pragma unroll
    for (int v = 0; v < 16; v++) { ar[v] = 0.f; ai[v] = 0.f; }
    if (T == 0) ar[0] = 1.0f;   // |0...0>, phase-1 layout: i = (T<<4)|v

#pragma unroll 1
    for (int layer = 0; layer < NLAYERS; layer++) {
        const cpx (*GL)[4] = gates + layer * NQ;   // qubit q at global bit 13-q

        // ===== Phase 1: local v-bits at global bits 0..3  (qubits 13..10)
        apply_gate<0>(ar, ai, GL[13]);
        apply_gate<1>(ar, ai, GL[12]);
        apply_gate<2>(ar, ai, GL[11]);
        apply_gate<3>(ar, ai, GL[10]);

        // exchange P1 -> P2 (v moves to bits 4..7)
#pragma unroll
        for (int v = 0; v < 16; v++) {
            const int p = swz((T << 4) | v);
            re[p] = ar[v]; im[p] = ai[v];
        }
        __syncthreads();
        {
            const int base = ((T >> 4) << 8) | (T & 15);
#pragma unroll
            for (int v = 0; v < 16; v++) {
                const int p = swz(base | (v << 4));
                ar[v] = re[p]; ai[v] = im[p];
            }
        }
        __syncthreads();

        // ===== Phase 2: bits 4..7 (qubits 9..6)
        apply_gate<0>(ar, ai, GL[9]);
        apply_gate<1>(ar, ai, GL[8]);
        apply_gate<2>(ar, ai, GL[7]);
        apply_gate<3>(ar, ai, GL[6]);

        // exchange P2 -> P3 (v moves to bits 8..11)
        {
            const int base = ((T >> 4) << 8) | (T & 15);
#pragma unroll
            for (int v = 0; v < 16; v++) {
                const int p = swz(base | (v << 4));
                re[p] = ar[v]; im[p] = ai[v];
            }
        }
        __syncthreads();
        {
            const int base = ((T >> 8) << 12) | (T & 255);
#pragma unroll
            for (int v = 0; v < 16; v++) {
                const int p = swz(base | (v << 8));
                ar[v] = re[p]; ai[v] = im[p];
            }
        }
        __syncthreads();

        // ===== Phase 3: bits 8..11 (qubits 5..2)
        apply_gate<0>(ar, ai, GL[5]);
        apply_gate<1>(ar, ai, GL[4]);
        apply_gate<2>(ar, ai, GL[3]);
        apply_gate<3>(ar, ai, GL[2]);

        // exchange P3 -> P4 (v bits 2,3 -> global 12,13; v bits 0,1 -> global 0,1)
        {
            const int base = ((T >> 8) << 12) | (T & 255);
#pragma unroll
            for (int v = 0; v < 16; v++) {
                const int p = swz(base | (v << 8));
                re[p] = ar[v]; im[p] = ai[v];
            }
        }
        __syncthreads();
#pragma unroll
        for (int v = 0; v < 16; v++) {
            const int i = ((v & 12) << 10) | (T << 2) | (v & 3);
            ar[v] = re[swz(i)]; ai[v] = im[swz(i)];
        }
        __syncthreads();

        // ===== Phase 4: bits 12,13 (qubits 1,0); v-bit2 <-> bit12, v-bit3 <-> bit13
        apply_gate<2>(ar, ai, GL[1]);
        apply_gate<3>(ar, ai, GL[0]);

        // exchange P4 -> P1 with fused CNOT chain: out[i] = in[i ^ (i>>1)]
#pragma unroll
        for (int v = 0; v < 16; v++) {
            const int i = ((v & 12) << 10) | (T << 2) | (v & 3);
            re[swz(i)] = ar[v]; im[swz(i)] = ai[v];
        }
        __syncthreads();
#pragma unroll
        for (int v = 0; v < 16; v++) {
            const int i   = (T << 4) | v;
            const int src = i ^ (i >> 1);
            ar[v] = re[swz(src)]; ai[v] = im[swz(src)];
        }
        __syncthreads();
    }

    // ---- expectation <Z...Z> straight from registers (P1 layout: i=(T<<4)|v) ----
    float acc = 0.0f;
    const int pT = __popc(T) & 1;
#pragma unroll
    for (int v = 0; v < 16; v++) {
        const float p2 = ar[v] * ar[v] + ai[v] * ai[v];
        acc += ((pT ^ (__popc(v) & 1)) ? -p2 : p2);
    }
#pragma unroll
    for (int o = 16; o; o >>= 1) acc += __shfl_down_sync(0xffffffffu, acc, o);
    if ((T & 31) == 0) red[T >> 5] = acc;
    __syncthreads();
    if (T < 32) {
        float vv = red[T];
#pragma unroll
        for (int o = 16; o; o >>= 1) vv += __shfl_down_sync(0xffffffffu, vv, o);
        if (T == 0) out[b] = vv;
    }
}

extern "C" void kernel_launch(void* const* d_in, const int* in_sizes, int n_in,
                              void* d_out, int out_size) {
    const float* x      = (const float*)d_in[0];
    const float* thetas = (const float*)d_in[1];
    float* out          = (float*)d_out;

    const int smem_bytes = 2 * SSZ * (int)sizeof(float);  // 139264
    cudaFuncSetAttribute(qsim_kernel,
                         cudaFuncAttributeMaxDynamicSharedMemorySize, smem_bytes);
    qsim_kernel<<<64, NTHR, smem_bytes>>>(x, thetas, out);
}

// round 12
// speedup vs baseline: 2.6479x; 1.7774x over previous
#include <cuda_runtime.h>

#define NQ      14
#define NLAYERS 2
#define NTHR    1024
#define NGATES  (NLAYERS * NQ)
#define HDIM    8192                 // half-state: 2^13
#define SSZ     (HDIM + HDIM / 8)    // 9216 floats per array (pad-swizzle)
#define SWZ(i)  ((i) + ((i) >> 3))

struct cpx { float x, y; };

__device__ float4 g_scratch[64 * 8192];   // 8 MB: [batch][8192 float4] = 16384 cpx amps

__device__ __forceinline__ cpx cmul(cpx a, cpx b) {
    return { a.x * b.x - a.y * b.y, a.x * b.y + a.y * b.x };
}
__device__ __forceinline__ cpx cadd(cpx a, cpx b) {
    return { a.x + b.x, a.y + b.y };
}
__device__ __forceinline__ void mmul2(const cpx* A, const cpx* B, cpx* C) {
    C[0] = cadd(cmul(A[0], B[0]), cmul(A[1], B[2]));
    C[1] = cadd(cmul(A[0], B[1]), cmul(A[1], B[3]));
    C[2] = cadd(cmul(A[2], B[0]), cmul(A[3], B[2]));
    C[3] = cadd(cmul(A[2], B[1]), cmul(A[3], B[3]));
}

// Fused gate G = RX(t2)*RZ(t1)*RX(t0)*RZ(x2)*RY(x1)
__device__ __forceinline__ void fused_gate(float xb, const float* __restrict__ th, cpx* G) {
    const float x1 = asinf(xb);
    const float x2 = acosf(xb * xb);
    float s1, c1;  sincosf(0.5f * x1, &s1, &c1);
    float sz, cz;  sincosf(0.5f * x2, &sz, &cz);
    cpx M[4] = { { cz * c1, -sz * c1 }, { -cz * s1,  sz * s1 },
                 { cz * s1,  sz * s1 }, {  cz * c1,  sz * c1 } };
    float s0, c0;   sincosf(0.5f * th[0], &s0, &c0);
    float sr1, cr1; sincosf(0.5f * th[1], &sr1, &cr1);
    float s2, c2v;  sincosf(0.5f * th[2], &s2, &c2v);
    cpx RX0[4] = { { c0, 0.f }, { 0.f, -s0 }, { 0.f, -s0 }, { c0, 0.f } };
    cpx RZ1[4] = { { cr1, -sr1 }, { 0.f, 0.f }, { 0.f, 0.f }, { cr1, sr1 } };
    cpx RX2[4] = { { c2v, 0.f }, { 0.f, -s2 }, { 0.f, -s2 }, { c2v, 0.f } };
    cpx T1[4], T2[4];
    mmul2(RX0, M,  T1);
    mmul2(RZ1, T1, T2);
    mmul2(RX2, T2, G);
}

// In-register butterfly on local v-bit K (8 amps -> 4 pairs).
template <int K>
__device__ __forceinline__ void apply_gate8(float (&ar)[8], float (&ai)[8],
                                            const cpx* __restrict__ G) {
    const cpx g0 = G[0], g1 = G[1], g2 = G[2], g3 = G[3];
#pragma unroll
    for (int m = 0; m < 4; m++) {
        const int v0 = ((m >> K) << (K + 1)) | (m & ((1 << K) - 1));
        const int v1 = v0 | (1 << K);
        const float a_r = ar[v0], a_i = ai[v0];
        const float b_r = ar[v1], b_i = ai[v1];
        ar[v0] = g0.x * a_r - g0.y * a_i + g1.x * b_r - g1.y * b_i;
        ai[v0] = g0.x * a_i + g0.y * a_r + g1.x * b_i + g1.y * b_r;
        ar[v1] = g2.x * a_r - g2.y * a_i + g3.x * b_r - g3.y * b_i;
        ai[v1] = g2.x * a_i + g2.y * a_r + g3.x * b_i + g3.y * b_r;
    }
}

// ============================================================================
// K1: grid 128 = (batch b, half h = global bit 13).
// layer-0 product-state init -> layer-0 CNOT perm -> layer-1 gates on bits 0-12
// -> store half-state to g_scratch (layout: float2 index (h<<13)|j5).
// ============================================================================
__global__ __launch_bounds__(NTHR, 1)
void qsim_k1(const float* __restrict__ x, const float* __restrict__ thetas) {
    extern __shared__ float smem[];
    float* re = smem;          // [SSZ]
    float* im = smem + SSZ;    // [SSZ]
    __shared__ cpx gates[NGATES][4];

    const int blk = blockIdx.x;
    const int b   = blk >> 1;
    const int h   = blk & 1;
    const int T   = threadIdx.x;
    const float xb = x[b];

    if (T < NGATES) {
        const int layer = T / NQ;
        const int q     = T % NQ;
        cpx G[4];
        fused_gate(xb, thetas + (layer * NQ + q) * 3, G);
        gates[T][0] = G[0]; gates[T][1] = G[1];
        gates[T][2] = G[2]; gates[T][3] = G[3];
    }
    __syncthreads();

    // ---- layer-0 product state, built directly in P5 layout ----
    // global bit `bit` <-> qubit (13-bit); factor F(bit,v) = gates[13-bit][2v] (= G[v][0])
    // P5 layout: j5 = (T<<2) | (v&3) | ((v&4)<<10); bit13 = h
    float ar[8], ai[8];
    {
        cpx p = gates[0][2 * h];                 // bit 13 factor (qubit 0)
#pragma unroll
        for (int bit = 2; bit <= 11; bit++) {
            const int vb = (T >> (bit - 2)) & 1;
            const cpx f = gates[13 - bit][2 * vb];
            p = cmul(p, f);
        }
        cpx c01[4];
#pragma unroll
        for (int c = 0; c < 4; c++)              // bit0 -> q13, bit1 -> q12
            c01[c] = cmul(gates[13][2 * (c & 1)], gates[12][2 * ((c >> 1) & 1)]);
        const cpx f12[2] = { gates[1][0], gates[1][2] };   // bit12 -> q1
#pragma unroll
        for (int v = 0; v < 8; v++) {
            cpx t = cmul(cmul(p, c01[v & 3]), f12[(v >> 2) & 1]);
            ar[v] = t.x; ai[v] = t.y;
        }
    }

    // ---- layer-0 CNOT chain: dest j (P1 layout) <- src = j ^ (j>>1) ^ (h<<12) ----
#pragma unroll
    for (int v = 0; v < 8; v++) {
        const int j5 = (T << 2) | (v & 3) | ((v & 4) << 10);
        re[SWZ(j5)] = ar[v]; im[SWZ(j5)] = ai[v];
    }
    __syncthreads();
#pragma unroll
    for (int v = 0; v < 8; v++) {
        const int j   = (T << 3) | v;
        const int src = j ^ (j >> 1) ^ (h << 12);
        ar[v] = re[SWZ(src)]; ai[v] = im[SWZ(src)];
    }
    __syncthreads();

    // ---- layer 1: gates on bits 0..12 (qubits 13..1) ----
    const cpx (*G1)[4] = gates + NQ;

    // P1: v <-> bits 0,1,2 (qubits 13,12,11)
    apply_gate8<0>(ar, ai, G1[13]);
    apply_gate8<1>(ar, ai, G1[12]);
    apply_gate8<2>(ar, ai, G1[11]);

    // X12
#pragma unroll
    for (int v = 0; v < 8; v++) {
        const int j = (T << 3) | v;
        re[SWZ(j)] = ar[v]; im[SWZ(j)] = ai[v];
    }
    __syncthreads();
    const int b2 = ((T >> 3) << 6) | (T & 7);
#pragma unroll
    for (int v = 0; v < 8; v++) {
        const int j = b2 | (v << 3);
        ar[v] = re[SWZ(j)]; ai[v] = im[SWZ(j)];
    }
    __syncthreads();

    // P2: bits 3,4,5 (qubits 10,9,8)
    apply_gate8<0>(ar, ai, G1[10]);
    apply_gate8<1>(ar, ai, G1[9]);
    apply_gate8<2>(ar, ai, G1[8]);

    // X23
#pragma unroll
    for (int v = 0; v < 8; v++) {
        const int j = b2 | (v << 3);
        re[SWZ(j)] = ar[v]; im[SWZ(j)] = ai[v];
    }
    __syncthreads();
    const int b3 = ((T >> 6) << 9) | (T & 63);
#pragma unroll
    for (int v = 0; v < 8; v++) {
        const int j = b3 | (v << 6);
        ar[v] = re[SWZ(j)]; ai[v] = im[SWZ(j)];
    }
    __syncthreads();

    // P3: bits 6,7,8 (qubits 7,6,5)
    apply_gate8<0>(ar, ai, G1[7]);
    apply_gate8<1>(ar, ai, G1[6]);
    apply_gate8<2>(ar, ai, G1[5]);

    // X34
#pragma unroll
    for (int v = 0; v < 8; v++) {
        const int j = b3 | (v << 6);
        re[SWZ(j)] = ar[v]; im[SWZ(j)] = ai[v];
    }
    __syncthreads();
    const int b4 = ((T >> 9) << 12) | (T & 511);
#pragma unroll
    for (int v = 0; v < 8; v++) {
        const int j = b4 | (v << 9);
        ar[v] = re[SWZ(j)]; ai[v] = im[SWZ(j)];
    }
    __syncthreads();

    // P4: bits 9,10,11 (qubits 4,3,2)
    apply_gate8<0>(ar, ai, G1[4]);
    apply_gate8<1>(ar, ai, G1[3]);
    apply_gate8<2>(ar, ai, G1[2]);

    // X45 -> P5 layout
#pragma unroll
    for (int v = 0; v < 8; v++) {
        const int j = b4 | (v << 9);
        re[SWZ(j)] = ar[v]; im[SWZ(j)] = ai[v];
    }
    __syncthreads();
#pragma unroll
    for (int v = 0; v < 8; v++) {
        const int j5 = (T << 2) | (v & 3) | ((v & 4) << 10);
        ar[v] = re[SWZ(j5)]; ai[v] = im[SWZ(j5)];
    }

    // P5 local gate: bit 12 = qubit 1 (v-bit 2)
    apply_gate8<2>(ar, ai, G1[1]);

    // ---- store to scratch: float2 idx m = (h<<13)|j5 -> float4 idx m>>1 ----
    float4* dst = g_scratch + (size_t)b * 8192;
    const int f4b = (h << 12) | (T << 1);
    dst[f4b]            = make_float4(ar[0], ai[0], ar[1], ai[1]);
    dst[f4b + 1]        = make_float4(ar[2], ai[2], ar[3], ai[3]);
    dst[f4b | 2048]     = make_float4(ar[4], ai[4], ar[5], ai[5]);
    dst[(f4b | 2048)+1] = make_float4(ar[6], ai[6], ar[7], ai[7]);
}

// ============================================================================
// K2: grid 64. Apply qubit-0 (bit 13) gate across halves, fold final CNOT
// chain into the parity mask (parity(d) = popc(s & 0x1555) for s = d^(d>>1)),
// reduce to out[b].
// ============================================================================
__global__ __launch_bounds__(NTHR, 1)
void qsim_k2(const float* __restrict__ x, const float* __restrict__ thetas,
             float* __restrict__ out) {
    __shared__ float red[32];
    const int b = blockIdx.x;
    const int T = threadIdx.x;

    cpx G[4];   // layer-1 qubit-0 fused gate (all threads compute redundantly)
    fused_gate(x[b], thetas + (1 * NQ + 0) * 3, G);

    const float4* src = g_scratch + (size_t)b * 8192;
    float acc = 0.0f;
#pragma unroll
    for (int k = 0; k < 4; k++) {
        const int u = T + k * NTHR;          // float4 index within half
        const float4 A = src[u];             // half0: amps j=2u, 2u+1
        const float4 B = src[u + 4096];      // half1: amps j=2u, 2u+1
        const float s = (__popc(u & 0xAAA) & 1) ? -1.0f : 1.0f;

        // amp j = 2u  (a0=(A.x,A.y), a1=(B.x,B.y)) : sign +s
        {
            const float n0r = G[0].x * A.x - G[0].y * A.y + G[1].x * B.x - G[1].y * B.y;
            const float n0i = G[0].x * A.y + G[0].y * A.x + G[1].x * B.y + G[1].y * B.x;
            const float n1r = G[2].x * A.x - G[2].y * A.y + G[3].x * B.x - G[3].y * B.y;
            const float n1i = G[2].x * A.y + G[2].y * A.x + G[3].x * B.y + G[3].y * B.x;
            acc += s * (n0r * n0r + n0i * n0i + n1r * n1r + n1i * n1i);
        }
        // amp j = 2u+1 (a0=(A.z,A.w), a1=(B.z,B.w)) : sign -s (bit0 in mask)
        {
            const float n0r = G[0].x * A.z - G[0].y * A.w + G[1].x * B.z - G[1].y * B.w;
            const float n0i = G[0].x * A.w + G[0].y * A.z + G[1].x * B.w + G[1].y * B.z;
            const float n1r = G[2].x * A.z - G[2].y * A.w + G[3].x * B.z - G[3].y * B.w;
            const float n1i = G[2].x * A.w + G[2].y * A.z + G[3].x * B.w + G[3].y * B.z;
            acc -= s * (n0r * n0r + n0i * n0i + n1r * n1r + n1i * n1i);
        }
    }

#pragma unroll
    for (int o = 16; o; o >>= 1) acc += __shfl_down_sync(0xffffffffu, acc, o);
    if ((T & 31) == 0) red[T >> 5] = acc;
    __syncthreads();
    if (T < 32) {
        float v = red[T];
#pragma unroll
        for (int o = 16; o; o >>= 1) v += __shfl_down_sync(0xffffffffu, v, o);
        if (T == 0) out[b] = v;
    }
}

extern "C" void kernel_launch(void* const* d_in, const int* in_sizes, int n_in,
                              void* d_out, int out_size) {
    const float* x      = (const float*)d_in[0];
    const float* thetas = (const float*)d_in[1];
    float* out          = (float*)d_out;

    const int smem_bytes = 2 * SSZ * (int)sizeof(float);  // 73728
    cudaFuncSetAttribute(qsim_k1,
                         cudaFuncAttributeMaxDynamicSharedMemorySize, smem_bytes);
    qsim_k1<<<128, NTHR, smem_bytes>>>(x, thetas);
    qsim_k2<<<64, NTHR>>>(x, thetas, out);
}

// round 14
// speedup vs baseline: 5.0494x; 1.9070x over previous
#include <cuda_runtime.h>
#include <cstdint>

#define NQ      14
#define NTHR    1024
#define NGATES  (2 * NQ)
#define HDIM    8192                  // half-state: 2^13
#define SSZ     (HDIM + HDIM / 32)    // 8448 floats per array (pad-swizzle)
#define SWZ(i)  ((i) + ((i) >> 5))

struct cpx { float x, y; };

__device__ __forceinline__ cpx cmul(cpx a, cpx b) {
    return { a.x * b.x - a.y * b.y, a.x * b.y + a.y * b.x };
}
__device__ __forceinline__ cpx cadd(cpx a, cpx b) {
    return { a.x + b.x, a.y + b.y };
}
__device__ __forceinline__ void mmul2(const cpx* A, const cpx* B, cpx* C) {
    C[0] = cadd(cmul(A[0], B[0]), cmul(A[1], B[2]));
    C[1] = cadd(cmul(A[0], B[1]), cmul(A[1], B[3]));
    C[2] = cadd(cmul(A[2], B[0]), cmul(A[3], B[2]));
    C[3] = cadd(cmul(A[2], B[1]), cmul(A[3], B[3]));
}

// Fused gate G = RX(t2)*RZ(t1)*RX(t0)*RZ(x2)*RY(x1)
__device__ __forceinline__ void fused_gate(float xb, const float* __restrict__ th, cpx* G) {
    const float x1 = asinf(xb);
    const float x2 = acosf(xb * xb);
    float s1, c1;  sincosf(0.5f * x1, &s1, &c1);
    float sz, cz;  sincosf(0.5f * x2, &sz, &cz);
    cpx M[4] = { { cz * c1, -sz * c1 }, { -cz * s1,  sz * s1 },
                 { cz * s1,  sz * s1 }, {  cz * c1,  sz * c1 } };
    float s0, c0;   sincosf(0.5f * th[0], &s0, &c0);
    float sr1, cr1; sincosf(0.5f * th[1], &sr1, &cr1);
    float s2, c2v;  sincosf(0.5f * th[2], &s2, &c2v);
    cpx RX0[4] = { { c0, 0.f }, { 0.f, -s0 }, { 0.f, -s0 }, { c0, 0.f } };
    cpx RZ1[4] = { { cr1, -sr1 }, { 0.f, 0.f }, { 0.f, 0.f }, { cr1, sr1 } };
    cpx RX2[4] = { { c2v, 0.f }, { 0.f, -s2 }, { 0.f, -s2 }, { c2v, 0.f } };
    cpx T1[4], T2[4];
    mmul2(RX0, M,  T1);
    mmul2(RZ1, T1, T2);
    mmul2(RX2, T2, G);
}

// In-register butterfly on local v-bit K (8 amps -> 4 pairs).
template <int K>
__device__ __forceinline__ void apply_gate8(float (&ar)[8], float (&ai)[8],
                                            const cpx* __restrict__ G) {
    const cpx g0 = G[0], g1 = G[1], g2 = G[2], g3 = G[3];
#pragma unroll
    for (int m = 0; m < 4; m++) {
        const int v0 = ((m >> K) << (K + 1)) | (m & ((1 << K) - 1));
        const int v1 = v0 | (1 << K);
        const float a_r = ar[v0], a_i = ai[v0];
        const float b_r = ar[v1], b_i = ai[v1];
        ar[v0] = g0.x * a_r - g0.y * a_i + g1.x * b_r - g1.y * b_i;
        ai[v0] = g0.x * a_i + g0.y * a_r + g1.x * b_i + g1.y * b_r;
        ar[v1] = g2.x * a_r - g2.y * a_i + g3.x * b_r - g3.y * b_i;
        ai[v1] = g2.x * a_i + g2.y * a_r + g3.x * b_i + g3.y * b_r;
    }
}

__device__ __forceinline__ uint32_t smem_u32(const void* p) {
    uint32_t a;
    asm("{ .reg .u64 t; cvta.to.shared.u64 t, %1; cvt.u32.u64 %0, t; }"
        : "=r"(a) : "l"(p));
    return a;
}

// ============================================================================
// Single kernel, grid 128 = (batch b, half h = global bit 13), cluster of 2.
// Layer-0 product state with CNOT chain folded analytically; layer-1 reduced
// to gates on even global bits (odd-bit gates drop out of the observable);
// final CNOT chain folded into parity mask 0x1555. Rank 1 PUSHES its partial
// into rank 0's SMEM before the cluster barrier (no remote read after exit).
// ============================================================================
__global__ __launch_bounds__(NTHR, 1) __cluster_dims__(2, 1, 1)
void qsim_kernel(const float* __restrict__ x,
                 const float* __restrict__ thetas,
                 float* __restrict__ out) {
    extern __shared__ float smem[];
    float* re = smem;          // [SSZ]
    float* im = smem + SSZ;    // [SSZ]
    __shared__ cpx gates[NGATES][4];
    __shared__ float red[32];
    __shared__ float partial_other;   // rank 1 deposits here (in rank 0's SMEM)

    const int blk = blockIdx.x;
    const int b   = blk >> 1;
    const int h   = blk & 1;          // global bit 13
    const int T   = threadIdx.x;

    if (T < NGATES) {
        cpx G[4];
        fused_gate(x[b], thetas + T * 3, G);
        gates[T][0] = G[0]; gates[T][1] = G[1];
        gates[T][2] = G[2]; gates[T][3] = G[3];
    }
    __syncthreads();

    // ---- layer-0 product state with layer-0 CNOT chain folded in ----
    // amp(m) = prod_bit gates[13-bit][2*src_bit],  src = m ^ (m>>1)
    // Layout A: m bits — [0]=v0 [1]=t0 [2]=v1 [3]=t1 [4]=v2 [5..12]=t2..t9 [13]=h
    float ar[8], ai[8];
    {
        const int t0 = T & 1, t1 = (T >> 1) & 1, t2 = (T >> 2) & 1;
        const int mhi   = ((T >> 2) << 5) | (h << 13);
        const int srchi = mhi ^ (mhi >> 1);

        cpx base = gates[13 - 5][2 * ((srchi >> 5) & 1)];
#pragma unroll
        for (int bit = 6; bit <= 13; bit++)
            base = cmul(base, gates[13 - bit][2 * ((srchi >> bit) & 1)]);

#pragma unroll
        for (int v2 = 0; v2 < 2; v2++) {
            // src_3 = t1^v2 (qubit 10), src_4 = v2^t2 (qubit 9)
            cpx b2 = cmul(cmul(base, gates[10][2 * (t1 ^ v2)]),
                          gates[9][2 * (v2 ^ t2)]);
#pragma unroll
            for (int v1 = 0; v1 < 2; v1++) {
                // src_1 = t0^v1 (qubit 12), src_2 = v1^t1 (qubit 11)
                cpx b21 = cmul(cmul(b2, gates[12][2 * (t0 ^ v1)]),
                               gates[11][2 * (v1 ^ t1)]);
#pragma unroll
                for (int v0 = 0; v0 < 2; v0++) {
                    // src_0 = v0^t0 (qubit 13)
                    cpx a = cmul(b21, gates[13][2 * (v0 ^ t0)]);
                    const int v = v0 | (v1 << 1) | (v2 << 2);
                    ar[v] = a.x; ai[v] = a.y;
                }
            }
        }
    }

    // ---- layer 1: only gates on even global bits matter ----
    const cpx (*G1)[4] = gates + NQ;    // qubit q at global bit 13-q

    // Phase A: v-bits <-> global bits {0,2,4} = qubits {13,11,9}
    apply_gate8<0>(ar, ai, G1[13]);
    apply_gate8<1>(ar, ai, G1[11]);
    apply_gate8<2>(ar, ai, G1[9]);

    // Exchange A -> B
    const int jAb = ((T & 1) << 1) | ((T & 2) << 2) | ((T & 4) << 3) | ((T >> 3) << 6);
#pragma unroll
    for (int v = 0; v < 8; v++) {
        const int j = jAb | (v & 1) | ((v & 2) << 1) | ((v & 4) << 2);
        re[SWZ(j)] = ar[v]; im[SWZ(j)] = ai[v];
    }
    __syncthreads();
    const int jBb = (T & 63) | (((T >> 6) & 1) << 7) | (((T >> 7) & 1) << 9)
                  | (((T >> 8) & 1) << 11) | (((T >> 9) & 1) << 12);
#pragma unroll
    for (int v = 0; v < 8; v++) {
        const int j = jBb | ((v & 1) << 6) | ((v & 2) << 7) | ((v & 4) << 8);
        ar[v] = re[SWZ(j)]; ai[v] = im[SWZ(j)];
    }
    __syncthreads();

    // Phase B: v-bits <-> global bits {6,8,10} = qubits {7,5,3}
    apply_gate8<0>(ar, ai, G1[7]);
    apply_gate8<1>(ar, ai, G1[5]);
    apply_gate8<2>(ar, ai, G1[3]);

    // Exchange B -> C
#pragma unroll
    for (int v = 0; v < 8; v++) {
        const int j = jBb | ((v & 1) << 6) | ((v & 2) << 7) | ((v & 4) << 8);
        re[SWZ(j)] = ar[v]; im[SWZ(j)] = ai[v];
    }
    __syncthreads();
#pragma unroll
    for (int v = 0; v < 8; v++) {
        const int j = (v & 3) | (T << 2) | ((v & 4) << 10);   // v0@0, v1@1, t0..t9@2..11, v2@12
        ar[v] = re[SWZ(j)]; ai[v] = im[SWZ(j)];
    }

    // Phase C: v-bit 2 <-> global bit 12 = qubit 1
    apply_gate8<2>(ar, ai, G1[1]);

    // ---- measurement: sign = parity(m & 0x1555); bit13 (=h) not in mask ----
    // Layout C mask bits: v0@0, t0@2, t2@4, t4@6, t6@8, t8@10, v2@12
    const int pT = __popc(T & 0x155) & 1;
    float acc = 0.0f;
#pragma unroll
    for (int v = 0; v < 8; v++) {
        const float p2 = ar[v] * ar[v] + ai[v] * ai[v];
        acc += (((v & 1) ^ ((v >> 2) & 1) ^ pT) ? -p2 : p2);
    }
#pragma unroll
    for (int o = 16; o; o >>= 1) acc += __shfl_down_sync(0xffffffffu, acc, o);
    if ((T & 31) == 0) red[T >> 5] = acc;
    __syncthreads();

    float total = 0.0f;
    if (T < 32) {
        float vv = red[T];
#pragma unroll
        for (int o = 16; o; o >>= 1) vv += __shfl_down_sync(0xffffffffu, vv, o);
        total = vv;   // valid on T==0
    }

    // ---- combine halves: rank 1 PUSHES its partial into rank 0's SMEM,
    //      then cluster barrier (arrive=release / wait=acquire), rank 0 reads
    //      LOCALLY. No remote access after the barrier -> peer may exit. ----
    if (h == 1 && T == 0) {
        const uint32_t laddr = smem_u32(&partial_other);
        uint32_t raddr;
        asm volatile("mapa.shared::cluster.u32 %0, %1, %2;"
                     : "=r"(raddr) : "r"(laddr), "r"(0));
        asm volatile("st.shared::cluster.f32 [%0], %1;"
                     :: "r"(raddr), "f"(total) : "memory");
    }
    asm volatile("barrier.cluster.arrive.aligned;" ::: "memory");
    asm volatile("barrier.cluster.wait.aligned;" ::: "memory");
    if (h == 0 && T == 0)
        out[b] = total + partial_other;
}

extern "C" void kernel_launch(void* const* d_in, const int* in_sizes, int n_in,
                              void* d_out, int out_size) {
    const float* x      = (const float*)d_in[0];
    const float* thetas = (const float*)d_in[1];
    float* out          = (float*)d_out;

    const int smem_bytes = 2 * SSZ * (int)sizeof(float);  // 67584
    cudaFuncSetAttribute(qsim_kernel,
                         cudaFuncAttributeMaxDynamicSharedMemorySize, smem_bytes);
    qsim_kernel<<<128, NTHR, smem_bytes>>>(x, thetas, out);
}

// round 15
// speedup vs baseline: 8.0417x; 1.5926x over previous
#include <cuda_runtime.h>

#define NQ 14

struct cpx { float x, y; };

__device__ __forceinline__ cpx cmul(cpx a, cpx b) {
    return { a.x * b.x - a.y * b.y, a.x * b.y + a.y * b.x };
}
__device__ __forceinline__ cpx cadd(cpx a, cpx b) {
    return { a.x + b.x, a.y + b.y };
}
__device__ __forceinline__ void mmul2(const cpx* A, const cpx* B, cpx* C) {
    C[0] = cadd(cmul(A[0], B[0]), cmul(A[1], B[2]));
    C[1] = cadd(cmul(A[0], B[1]), cmul(A[1], B[3]));
    C[2] = cadd(cmul(A[2], B[0]), cmul(A[3], B[2]));
    C[3] = cadd(cmul(A[2], B[1]), cmul(A[3], B[3]));
}

// Fused gate G = RX(t2)*RZ(t1)*RX(t0)*RZ(x2)*RY(x1)   (validated R10-R14)
__device__ __forceinline__ void fused_gate(float xb, const float* __restrict__ th, cpx* G) {
    const float x1 = asinf(xb);
    const float x2 = acosf(xb * xb);
    float s1, c1;  sincosf(0.5f * x1, &s1, &c1);
    float sz, cz;  sincosf(0.5f * x2, &sz, &cz);
    cpx M[4] = { { cz * c1, -sz * c1 }, { -cz * s1,  sz * s1 },
                 { cz * s1,  sz * s1 }, {  cz * c1,  sz * c1 } };
    float s0, c0;   sincosf(0.5f * th[0], &s0, &c0);
    float sr1, cr1; sincosf(0.5f * th[1], &sr1, &cr1);
    float s2, c2v;  sincosf(0.5f * th[2], &s2, &c2v);
    cpx RX0[4] = { { c0, 0.f }, { 0.f, -s0 }, { 0.f, -s0 }, { c0, 0.f } };
    cpx RZ1[4] = { { cr1, -sr1 }, { 0.f, 0.f }, { 0.f, 0.f }, { cr1, sr1 } };
    cpx RX2[4] = { { c2v, 0.f }, { 0.f, -s2 }, { 0.f, -s2 }, { c2v, 0.f } };
    cpx T1[4], T2[4];
    mmul2(RX0, M,  T1);
    mmul2(RZ1, T1, T2);
    mmul2(RX2, T2, G);
}

// ============================================================================
// Transfer-matrix formulation.
//
// After folding both CNOT chains (first into the layer-0 product state via
// src = m^(m>>1), second into the parity mask 0x1555 = even bits) and dropping
// the layer-1 gates on odd bits (they provably cancel in the observable —
// validated R12-R14), the expectation factorizes over even bits:
//
//   E = sum_{odd bits o} |F13(o13)|^2 * prod_{j even} ( |u_j(0)|^2 - |u_j(1)|^2 )
//   u_j = G_j * g_j ;  g_0(e) = F0(e^o1) ;  g_j(e) = F_{j-1}(o_{j-1}^e)*F_j(e^o_{j+1})
//   F_k(s) = layer-0 fused gate of qubit 13-k, column 0, entry s
//   G_j    = layer-1 fused gate of qubit 13-j
//
// This is a chain over the 7 odd bits -> contract 6 2x2 transfer matrices.
// One warp per batch element.
// ============================================================================
__global__ __launch_bounds__(32, 1)
void qsim_tiny(const float* __restrict__ x,
               const float* __restrict__ thetas,
               float* __restrict__ out) {
    __shared__ cpx   sF[14][2];   // sF[q][s]: layer-0 gate of qubit q, col 0
    __shared__ cpx   sH[7][4];    // sH[i]: layer-1 gate of qubit 13-2i (bit 2i)
    __shared__ float sW[7][4];    // weight tables w_i[a*2+b]

    const int b    = blockIdx.x;
    const int lane = threadIdx.x;
    const float xb = x[b];

    if (lane < 14) {
        cpx G[4];
        fused_gate(xb, thetas + lane * 3, G);            // layer 0, qubit = lane
        sF[lane][0] = G[0];                              // G[0][0]
        sF[lane][1] = G[2];                              // G[1][0]
    } else if (lane < 21) {
        const int i = lane - 14;
        const int q = 13 - 2 * i;                        // qubit on even bit 2i
        cpx G[4];
        fused_gate(xb, thetas + (NQ + q) * 3, G);        // layer 1
        sH[i][0] = G[0]; sH[i][1] = G[1];
        sH[i][2] = G[2]; sH[i][3] = G[3];
    }
    __syncwarp();

    if (lane < 26) {
        int i, a, bb;
        if (lane < 2) { i = 0; a = 0; bb = lane; }
        else {
            const int idx = lane - 2;
            i  = 1 + (idx >> 2);
            a  = (idx >> 1) & 1;
            bb = idx & 1;
        }
        cpx g0, g1;
        if (i == 0) {                                    // bit 0: g(e) = Fq13[e^b]
            g0 = sF[13][bb];
            g1 = sF[13][1 ^ bb];
        } else {                                         // bit j=2i
            const int qa = 14 - 2 * i;                   // F_{j-1}: qubit 13-(2i-1)
            const int qb = 13 - 2 * i;                   // F_j    : qubit 13-2i
            g0 = cmul(sF[qa][a],     sF[qb][bb]);        // e=0
            g1 = cmul(sF[qa][a ^ 1], sF[qb][1 ^ bb]);    // e=1
        }
        const cpx h0 = sH[i][0], h1 = sH[i][1], h2 = sH[i][2], h3 = sH[i][3];
        const cpx u0 = cadd(cmul(h0, g0), cmul(h1, g1));
        const cpx u1 = cadd(cmul(h2, g0), cmul(h3, g1));
        sW[i][a * 2 + bb] = (u0.x * u0.x + u0.y * u0.y)
                          - (u1.x * u1.x + u1.y * u1.y);
    }
    __syncwarp();

    if (lane == 0) {
        float v0 = sW[0][0], v1 = sW[0][1];              // over o1
#pragma unroll
        for (int i = 1; i < 7; i++) {                    // contract o3..o13
            const float t0 = v0 * sW[i][0] + v1 * sW[i][2];
            const float t1 = v0 * sW[i][1] + v1 * sW[i][3];
            v0 = t0; v1 = t1;
        }
        const cpx f0 = sF[0][0], f1 = sF[0][1];          // tail |F13(o13)|^2
        out[b] = v0 * (f0.x * f0.x + f0.y * f0.y)
               + v1 * (f1.x * f1.x + f1.y * f1.y);
    }
}

extern "C" void kernel_launch(void* const* d_in, const int* in_sizes, int n_in,
                              void* d_out, int out_size) {
    const float* x      = (const float*)d_in[0];
    const float* thetas = (const float*)d_in[1];
    float* out          = (float*)d_out;
    qsim_tiny<<<64, 32>>>(x, thetas, out);
}